// round 6
// baseline (speedup 1.0000x reference)
#include <cuda_runtime.h>
#include <cstdint>

#define TU      204800     // 400 * 512 upsampled length
#define TBLK    400        // frames
#define BATCH   16
#define NH      9          // harmonic_num + 1
#define NROW1   12800      // TU / 16

// Level-1 inclusive prefix (cumsum of 16-sample row totals), per (b,h): 12800 each.
__device__ float g_P[BATCH * NH * NROW1];            // 7.4 MB
// Sequential multiples s_{k+1}(x) (acc=0 left-to-right), per (b,h,t): 16 each.
__device__ float g_seqx[BATCH * NH * TBLK * 16];     // 3.7 MB

// ---------------- threefry2x32, key = (0, 42) ----------------
__device__ __forceinline__ uint2 threefry_0_42(uint32_t x0, uint32_t x1) {
    const uint32_t ks0 = 0u;
    const uint32_t ks1 = 42u;
    const uint32_t ks2 = 0x1BD11BDAu ^ 42u;
    x0 += ks0; x1 += ks1;
#define TF_RND(r) { x0 += x1; x1 = __funnelshift_l(x1, x1, (r)); x1 ^= x0; }
    TF_RND(13) TF_RND(15) TF_RND(26) TF_RND(6)   x0 += ks1; x1 += ks2 + 1u;
    TF_RND(17) TF_RND(29) TF_RND(16) TF_RND(24)  x0 += ks2; x1 += ks0 + 2u;
    TF_RND(13) TF_RND(15) TF_RND(26) TF_RND(6)   x0 += ks0; x1 += ks1 + 3u;
    TF_RND(17) TF_RND(29) TF_RND(16) TF_RND(24)  x0 += ks1; x1 += ks2 + 4u;
    TF_RND(13) TF_RND(15) TF_RND(26) TF_RND(6)   x0 += ks2; x1 += ks0 + 5u;
#undef TF_RND
    return make_uint2(x0, x1);
}

// partitionable threefry bits, bit_width=32: bits1 ^ bits2, counter (0, n)
__device__ __forceinline__ uint32_t noise_bits(uint32_t n) {
    uint2 r = threefry_0_42(0u, n);
    return r.x ^ r.y;
}

// ---------------- jax.random.normal from raw bits (XLA ErfInv32 / Giles) ----------------
__device__ __forceinline__ float normal_from_bits(uint32_t bits) {
    float u01 = __uint_as_float((bits >> 9) | 0x3F800000u) - 1.0f;   // [0,1)
    const float lo = -0.99999994039535522461f;                        // nextafter(-1,0)
    float u = __fadd_rn(__fmul_rn(u01, 2.0f), lo);                    // == fma form (2u exact)
    u = fmaxf(lo, u);
    float w = -log1pf(-__fmul_rn(u, u));
    float p;
    if (w < 5.0f) {
        w = w - 2.5f;
        p = 2.81022636e-08f;
        p = fmaf(p, w, 3.43273939e-07f);
        p = fmaf(p, w, -3.5233877e-06f);
        p = fmaf(p, w, -4.39150654e-06f);
        p = fmaf(p, w, 0.00021858087f);
        p = fmaf(p, w, -0.00125372503f);
        p = fmaf(p, w, -0.00417768164f);
        p = fmaf(p, w, 0.246640727f);
        p = fmaf(p, w, 1.50140941f);
    } else {
        w = sqrtf(w) - 3.0f;
        p = -0.000200214257f;
        p = fmaf(p, w, 0.000100950558f);
        p = fmaf(p, w, 0.00134934322f);
        p = fmaf(p, w, -0.00367342844f);
        p = fmaf(p, w, 0.00573950773f);
        p = fmaf(p, w, -0.0076224613f);
        p = fmaf(p, w, 0.00943887047f);
        p = fmaf(p, w, 1.00167406f);
        p = fmaf(p, w, 2.83297682f);
    }
    return __fmul_rn(1.4142135623730951f, __fmul_rn(p, u));
}

// ---------------- accurate sine (exact Cody-Waite mod pi/2, fk < 2^16) ----------------
__device__ __forceinline__ float sin_acc(float y) {
    const float TWO_OVER_PI = 0.6366197723675814f;
    const float P1 = 1.5703125f;              // 201 * 2^-7
    const float P2 = 4.84466552734375e-4f;    // 254 * 2^-19
    const float P3 = -6.3975784e-7f;
    float fk = rintf(__fmul_rn(y, TWO_OVER_PI));
    float r = fmaf(fk, -P1, y);
    r = fmaf(fk, -P2, r);
    r = fmaf(fk, -P3, r);
    int q = ((int)fk) & 3;
    float s = __fmul_rn(r, r);
    float ps = 2.7557319223985893e-6f;
    ps = fmaf(ps, s, -1.984126984126984e-4f);
    ps = fmaf(ps, s, 8.333333333333333e-3f);
    ps = fmaf(ps, s, -1.6666666666666666e-1f);
    ps = __fmul_rn(r, fmaf(ps, s, 1.0f));
    float pc = -2.755731922398589e-7f;
    pc = fmaf(pc, s, 2.48015873015873e-5f);
    pc = fmaf(pc, s, -1.3888888888888889e-3f);
    pc = fmaf(pc, s, 4.1666666666666664e-2f);
    pc = fmaf(pc, s, -0.5f);
    pc = fmaf(pc, s, 1.0f);
    float v = (q & 1) ? pc : ps;
    return (q & 2) ? -v : v;
}

// ---------------- accurate tanh ----------------
__device__ __forceinline__ float tanh_acc(float z) {
    float a = fabsf(z) * 2.0f;
    a = fminf(a, 16.0f);
    float fk = rintf(__fmul_rn(a, 1.4426950408889634f));
    float f = fmaf(fk, -0.693359375f, a);
    f = fmaf(fk, 2.12194440054690583e-4f, f);
    float p = 1.9841269841269841e-4f;
    p = fmaf(p, f, 1.3888888888888889e-3f);
    p = fmaf(p, f, 8.333333333333333e-3f);
    p = fmaf(p, f, 4.1666666666666664e-2f);
    p = fmaf(p, f, 1.6666666666666666e-1f);
    p = fmaf(p, f, 0.5f);
    p = fmaf(p, f, 1.0f);
    p = fmaf(p, f, 1.0f);
    float e = __fmul_rn(p, (float)(1u << (int)fk));
    float th = __fdiv_rn(e - 1.0f, e + 1.0f);
    return (z < 0.0f) ? -th : th;
}

// ---------------- Kernel 1: XLA ReduceWindowRewriter radix-16 scan ----------------
// cumsum(v[0..n)) := if n<=16: sequential (acc=0, left->right)
//                    else: rows of 16; inner = sequential row scans;
//                          O = cumsum(row totals); out = fl(inner + O[row-1])
// Levels for 204800: 12800 -> 800 -> 50 (pad to 64) -> 4 (sequential).
// One CTA per (b,h). Emits g_seqx (level-0 inner scans; block-constant) and g_P
// (level-1 prefix over 12800 rows).
__global__ void scan16_kernel(const float* __restrict__ f0) {
    __shared__ float sm16[TBLK];      // T1val(t) = s16(x_t)  (row total, level 0)
    __shared__ float U[TBLK];         // T2val(t) = s16(sm16[t])
    __shared__ float smT1[TBLK * 16]; // s_{k+1}(sm16[t])  (level-1 inner scans)
    __shared__ float inner3[800];     // level-2 inner scans over T2
    __shared__ float O2s[800];        // cumsum over 800 T2 values
    __shared__ float T3[50];
    __shared__ float O3s[50];         // cumsum over 50 T3 values
    __shared__ float inner4[50];

    const int row = blockIdx.x;                 // 0..143 = b*9+h
    const int b = row / NH, h = row % NH;
    const float m = (float)(h + 1);

    // x_t = fl(fl(f0/48000)*m); sequential multiples s_1..s_16 (acc starts at 0).
    for (int t = threadIdx.x; t < TBLK; t += blockDim.x) {
        float x = __fmul_rn(__fdiv_rn(f0[b * TBLK + t], 48000.0f), m);
        float s = 0.0f;
#pragma unroll
        for (int k = 0; k < 16; k++) {
            s = __fadd_rn(s, x);
            g_seqx[(row * TBLK + t) * 16 + k] = s;
        }
        sm16[t] = s;
    }
    __syncthreads();

    // Level-1 inner scans: 16 equal values sm16[t] per row (t = R>>5 constant per row).
    for (int t = threadIdx.x; t < TBLK; t += blockDim.x) {
        float v = sm16[t], s = 0.0f;
#pragma unroll
        for (int k = 0; k < 16; k++) {
            s = __fadd_rn(s, v);
            smT1[t * 16 + k] = s;
        }
        U[t] = s;
    }
    __syncthreads();

    // Level-2 inner scans over T2[R2] = U[R2>>1] (values come in equal pairs).
    for (int R3 = threadIdx.x; R3 < 50; R3 += blockDim.x) {
        float s = 0.0f;
        for (int j = 0; j < 16; j++) {
            s = __fadd_rn(s, U[(16 * R3 + j) >> 1]);
            inner3[R3 * 16 + j] = s;
        }
        T3[R3] = s;
    }
    __syncthreads();

    // Level-3: cumsum over 50 T3 values: pad to [4,16] with zeros, inner seq scans,
    // then sequential scan of the 4 row totals (base case).
    if (threadIdx.x == 0) {
        float T4[4], O4[4];
        for (int r = 0; r < 4; r++) {
            float s = 0.0f;
            for (int j = 0; j < 16; j++) {
                int idx = 16 * r + j;
                float v = (idx < 50) ? T3[idx] : 0.0f;
                s = __fadd_rn(s, v);
                if (idx < 50) inner4[idx] = s;
            }
            T4[r] = s;
        }
        float s = 0.0f;
        for (int r = 0; r < 4; r++) { s = __fadd_rn(s, T4[r]); O4[r] = s; }
        for (int i = 0; i < 50; i++) {
            float e = ((i >> 4) == 0) ? 0.0f : O4[(i >> 4) - 1];
            O3s[i] = __fadd_rn(inner4[i], e);
        }
    }
    __syncthreads();

    // O2 (cumsum over 800): fl(inner3 + excl O3)
    for (int i2 = threadIdx.x; i2 < 800; i2 += blockDim.x) {
        float e = ((i2 >> 4) == 0) ? 0.0f : O3s[(i2 >> 4) - 1];
        O2s[i2] = __fadd_rn(inner3[i2], e);
    }
    __syncthreads();

    // P (cumsum over 12800 row totals): fl(inner2 + excl O2),
    // inner2[R] = s_{(R&15)+1}(sm16[R>>5]) = smT1[(R>>5)*16 + (R&15)].
    for (int R = threadIdx.x; R < NROW1; R += blockDim.x) {
        int t = R >> 5, k = R & 15, R2 = R >> 4;
        float e = (R2 == 0) ? 0.0f : O2s[R2 - 1];
        g_P[row * NROW1 + R] = __fadd_rn(smT1[t * 16 + k], e);
    }
}

// ---------------- Kernel 2: per-sample C = fl(inner0 + excl P) + sin + noise + merge ----------------
__global__ void __launch_bounds__(256) nsf_kernel(const float* __restrict__ f0,
                                                  const float* __restrict__ W,
                                                  const float* __restrict__ bias,
                                                  float* __restrict__ out) {
    const int g = blockIdx.x * blockDim.x + threadIdx.x;
    if (g >= BATCH * TU) return;
    const int b = g / TU;
    const int s = g - b * TU;
    const int t = s >> 9;
    const int R = s >> 4;
    const int j = s & 15;

    const float f0t  = __ldg(&f0[b * TBLK + t]);
    const bool voiced = (f0t > 1.0f);
    const float uv   = voiced ? 1.0f : 0.0f;
    const float namp = voiced ? 0.003f : (float)(0.1 / 3.0);

    float acc = 0.0f;
#pragma unroll
    for (int h = 0; h < NH; h++) {
        const int row = b * NH + h;
        const float inner0 = __ldg(&g_seqx[(row * TBLK + t) * 16 + j]);
        const float pre = (R == 0) ? 0.0f : __ldg(&g_P[row * NROW1 + R - 1]);
        const float C = __fadd_rn(inner0, pre);

        const float phase = __fmul_rn(C, 6.283185307179586f);
        const float sw = __fmul_rn(sin_acc(phase), 0.1f);

        const uint32_t bits = noise_bits((uint32_t)(g * NH + h));
        const float nz = __fmul_rn(namp, normal_from_bits(bits));

        const float src = __fadd_rn(__fmul_rn(sw, uv), nz);
        acc = fmaf(src, __ldg(&W[h]), acc);
    }
    out[g] = tanh_acc(__fadd_rn(acc, __ldg(&bias[0])));
}

extern "C" void kernel_launch(void* const* d_in, const int* in_sizes, int n_in,
                              void* d_out, int out_size) {
    const float* f0 = (const float*)d_in[0];
    const float* W;
    const float* bias;
    if (n_in >= 4 && in_sizes[2] == NH)      { W = (const float*)d_in[2]; bias = (const float*)d_in[3]; }
    else if (n_in >= 3 && in_sizes[1] == NH) { W = (const float*)d_in[1]; bias = (const float*)d_in[2]; }
    else                                     { W = (const float*)d_in[2]; bias = (const float*)d_in[3]; }
    float* out = (float*)d_out;

    scan16_kernel<<<BATCH * NH, 256>>>(f0);
    const int total = BATCH * TU;
    nsf_kernel<<<(total + 255) / 256, 256>>>(f0, W, bias, out);
}

// round 7
// speedup vs baseline: 1.2131x; 1.2131x over previous
#include <cuda_runtime.h>
#include <cstdint>

#define TU      204800     // 400 * 512 upsampled length
#define TBLK    400        // frames
#define BATCH   16
#define NH      9          // harmonic_num + 1
#define NROW1   12800      // TU / 16

// Level-1 inclusive prefix (cumsum of 16-sample row totals), per (b,h): 12800 each.
__device__ float g_P[BATCH * NH * NROW1];            // 7.4 MB
// Sequential multiples s_{k+1}(x) (acc=0 left-to-right), per (b,h,t): 16 each.
__device__ float g_seqx[BATCH * NH * TBLK * 16];     // 3.7 MB

// ---------------- threefry2x32, key = (0, 42) ----------------
__device__ __forceinline__ uint2 threefry_0_42(uint32_t x0, uint32_t x1) {
    const uint32_t ks0 = 0u;
    const uint32_t ks1 = 42u;
    const uint32_t ks2 = 0x1BD11BDAu ^ 42u;
    x0 += ks0; x1 += ks1;
#define TF_RND(r) { x0 += x1; x1 = __funnelshift_l(x1, x1, (r)); x1 ^= x0; }
    TF_RND(13) TF_RND(15) TF_RND(26) TF_RND(6)   x0 += ks1; x1 += ks2 + 1u;
    TF_RND(17) TF_RND(29) TF_RND(16) TF_RND(24)  x0 += ks2; x1 += ks0 + 2u;
    TF_RND(13) TF_RND(15) TF_RND(26) TF_RND(6)   x0 += ks0; x1 += ks1 + 3u;
    TF_RND(17) TF_RND(29) TF_RND(16) TF_RND(24)  x0 += ks1; x1 += ks2 + 4u;
    TF_RND(13) TF_RND(15) TF_RND(26) TF_RND(6)   x0 += ks2; x1 += ks0 + 5u;
#undef TF_RND
    return make_uint2(x0, x1);
}

// partitionable threefry bits, bit_width=32: bits1 ^ bits2, counter (0, n)
__device__ __forceinline__ uint32_t noise_bits(uint32_t n) {
    uint2 r = threefry_0_42(0u, n);
    return r.x ^ r.y;
}

// ---------------- fast helpers (MUFU), accuracy >> required budget ----------------
__device__ __forceinline__ float mufu_sin(float r) {
    float v; asm("sin.approx.f32 %0, %1;" : "=f"(v) : "f"(r)); return v;
}
__device__ __forceinline__ float mufu_lg2(float t) {
    float v; asm("lg2.approx.f32 %0, %1;" : "=f"(v) : "f"(t)); return v;
}

// ---------------- jax.random.normal from raw bits (Giles poly; fast log) ----------------
// Noise values are scaled by 0.003 (or 0.0333 on 0.25% of samples); w needs only
// ~1e-4 relative accuracy, so lg2.approx (rel err ~2e-7) replaces log1pf.
__device__ __forceinline__ float normal_from_bits(uint32_t bits) {
    float u01 = __uint_as_float((bits >> 9) | 0x3F800000u) - 1.0f;   // [0,1)
    const float lo = -0.99999994039535522461f;                        // nextafter(-1,0)
    float u = __fadd_rn(__fmul_rn(u01, 2.0f), lo);
    u = fmaxf(lo, u);
    float t = fmaf(-u, u, 1.0f);                                      // 1 - u^2 (>=2^-25)
    float w = __fmul_rn(mufu_lg2(t), -0.6931471805599453f);           // -ln(1-u^2)
    float p;
    if (w < 5.0f) {
        w = w - 2.5f;
        p = 2.81022636e-08f;
        p = fmaf(p, w, 3.43273939e-07f);
        p = fmaf(p, w, -3.5233877e-06f);
        p = fmaf(p, w, -4.39150654e-06f);
        p = fmaf(p, w, 0.00021858087f);
        p = fmaf(p, w, -0.00125372503f);
        p = fmaf(p, w, -0.00417768164f);
        p = fmaf(p, w, 0.246640727f);
        p = fmaf(p, w, 1.50140941f);
    } else {
        w = sqrtf(w) - 3.0f;
        p = -0.000200214257f;
        p = fmaf(p, w, 0.000100950558f);
        p = fmaf(p, w, 0.00134934322f);
        p = fmaf(p, w, -0.00367342844f);
        p = fmaf(p, w, 0.00573950773f);
        p = fmaf(p, w, -0.0076224613f);
        p = fmaf(p, w, 0.00943887047f);
        p = fmaf(p, w, 1.00167406f);
        p = fmaf(p, w, 2.83297682f);
    }
    return __fmul_rn(1.4142135623730951f, __fmul_rn(p, u));
}

// ---------------- accurate-arg sine: exact Cody-Waite mod pi/2 (fk < 2^16) + MUFU ----------------
// Reduction error <= ~4e-8 rad; sin.approx on |r'|<=3pi/4 has abs err ~5e-7.
// Quadrant parity via sin(pi/2 - r) = cos(r).
__device__ __forceinline__ float sin_acc(float y) {
    const float TWO_OVER_PI = 0.6366197723675814f;
    const float P1 = 1.5703125f;              // 201 * 2^-7
    const float P2 = 4.84466552734375e-4f;    // 254 * 2^-19
    const float P3 = -6.3975784e-7f;
    float fk = rintf(__fmul_rn(y, TWO_OVER_PI));
    float r = fmaf(fk, -P1, y);
    r = fmaf(fk, -P2, r);
    r = fmaf(fk, -P3, r);
    int q = (int)fk;
    float rr = (q & 1) ? (1.5707963267948966f - r) : r;
    float v = mufu_sin(rr);
    return (q & 2) ? -v : v;
}

// ---------------- accurate tanh (unchanged; 1.2% of work, protects error margin) ----------------
__device__ __forceinline__ float tanh_acc(float z) {
    float a = fabsf(z) * 2.0f;
    a = fminf(a, 16.0f);
    float fk = rintf(__fmul_rn(a, 1.4426950408889634f));
    float f = fmaf(fk, -0.693359375f, a);
    f = fmaf(fk, 2.12194440054690583e-4f, f);
    float p = 1.9841269841269841e-4f;
    p = fmaf(p, f, 1.3888888888888889e-3f);
    p = fmaf(p, f, 8.333333333333333e-3f);
    p = fmaf(p, f, 4.1666666666666664e-2f);
    p = fmaf(p, f, 1.6666666666666666e-1f);
    p = fmaf(p, f, 0.5f);
    p = fmaf(p, f, 1.0f);
    p = fmaf(p, f, 1.0f);
    float e = __fmul_rn(p, (float)(1u << (int)fk));
    float th = __fdiv_rn(e - 1.0f, e + 1.0f);
    return (z < 0.0f) ? -th : th;
}

// ---------------- Kernel 1: XLA ReduceWindowRewriter radix-16 scan ----------------
__global__ void scan16_kernel(const float* __restrict__ f0) {
    __shared__ float sm16[TBLK];
    __shared__ float U[TBLK];
    __shared__ float smT1[TBLK * 16];
    __shared__ float inner3[800];
    __shared__ float O2s[800];
    __shared__ float T3[50];
    __shared__ float O3s[50];
    __shared__ float inner4[50];

    const int row = blockIdx.x;                 // 0..143 = b*9+h
    const int b = row / NH, h = row % NH;
    const float m = (float)(h + 1);

    for (int t = threadIdx.x; t < TBLK; t += blockDim.x) {
        float x = __fmul_rn(__fdiv_rn(f0[b * TBLK + t], 48000.0f), m);
        float s = 0.0f;
#pragma unroll
        for (int k = 0; k < 16; k++) {
            s = __fadd_rn(s, x);
            g_seqx[(row * TBLK + t) * 16 + k] = s;
        }
        sm16[t] = s;
    }
    __syncthreads();

    for (int t = threadIdx.x; t < TBLK; t += blockDim.x) {
        float v = sm16[t], s = 0.0f;
#pragma unroll
        for (int k = 0; k < 16; k++) {
            s = __fadd_rn(s, v);
            smT1[t * 16 + k] = s;
        }
        U[t] = s;
    }
    __syncthreads();

    for (int R3 = threadIdx.x; R3 < 50; R3 += blockDim.x) {
        float s = 0.0f;
        for (int j = 0; j < 16; j++) {
            s = __fadd_rn(s, U[(16 * R3 + j) >> 1]);
            inner3[R3 * 16 + j] = s;
        }
        T3[R3] = s;
    }
    __syncthreads();

    if (threadIdx.x == 0) {
        float T4[4], O4[4];
        for (int r = 0; r < 4; r++) {
            float s = 0.0f;
            for (int j = 0; j < 16; j++) {
                int idx = 16 * r + j;
                float v = (idx < 50) ? T3[idx] : 0.0f;
                s = __fadd_rn(s, v);
                if (idx < 50) inner4[idx] = s;
            }
            T4[r] = s;
        }
        float s = 0.0f;
        for (int r = 0; r < 4; r++) { s = __fadd_rn(s, T4[r]); O4[r] = s; }
        for (int i = 0; i < 50; i++) {
            float e = ((i >> 4) == 0) ? 0.0f : O4[(i >> 4) - 1];
            O3s[i] = __fadd_rn(inner4[i], e);
        }
    }
    __syncthreads();

    for (int i2 = threadIdx.x; i2 < 800; i2 += blockDim.x) {
        float e = ((i2 >> 4) == 0) ? 0.0f : O3s[(i2 >> 4) - 1];
        O2s[i2] = __fadd_rn(inner3[i2], e);
    }
    __syncthreads();

    for (int R = threadIdx.x; R < NROW1; R += blockDim.x) {
        int t = R >> 5, k = R & 15, R2 = R >> 4;
        float e = (R2 == 0) ? 0.0f : O2s[R2 - 1];
        g_P[row * NROW1 + R] = __fadd_rn(smT1[t * 16 + k], e);
    }
}

// ---------------- Kernel 2: per-sample C + sin + noise + merge + tanh ----------------
__global__ void __launch_bounds__(256) nsf_kernel(const float* __restrict__ f0,
                                                  const float* __restrict__ W,
                                                  const float* __restrict__ bias,
                                                  float* __restrict__ out) {
    const int g = blockIdx.x * blockDim.x + threadIdx.x;
    if (g >= BATCH * TU) return;
    const int b = g / TU;
    const int s = g - b * TU;
    const int t = s >> 9;
    const int R = s >> 4;
    const int j = s & 15;

    const float f0t  = __ldg(&f0[b * TBLK + t]);
    const bool voiced = (f0t > 1.0f);
    const float uv   = voiced ? 1.0f : 0.0f;
    const float namp = voiced ? 0.003f : (float)(0.1 / 3.0);

    float acc = 0.0f;
#pragma unroll
    for (int h = 0; h < NH; h++) {
        const int row = b * NH + h;
        const float inner0 = __ldg(&g_seqx[(row * TBLK + t) * 16 + j]);
        const float pre = (R == 0) ? 0.0f : __ldg(&g_P[row * NROW1 + R - 1]);
        const float C = __fadd_rn(inner0, pre);

        const float phase = __fmul_rn(C, 6.283185307179586f);
        const float sw = __fmul_rn(sin_acc(phase), 0.1f);

        const uint32_t bits = noise_bits((uint32_t)(g * NH + h));
        const float nz = __fmul_rn(namp, normal_from_bits(bits));

        const float src = __fadd_rn(__fmul_rn(sw, uv), nz);
        acc = fmaf(src, __ldg(&W[h]), acc);
    }
    out[g] = tanh_acc(__fadd_rn(acc, __ldg(&bias[0])));
}

extern "C" void kernel_launch(void* const* d_in, const int* in_sizes, int n_in,
                              void* d_out, int out_size) {
    const float* f0 = (const float*)d_in[0];
    const float* W;
    const float* bias;
    if (n_in >= 4 && in_sizes[2] == NH)      { W = (const float*)d_in[2]; bias = (const float*)d_in[3]; }
    else if (n_in >= 3 && in_sizes[1] == NH) { W = (const float*)d_in[1]; bias = (const float*)d_in[2]; }
    else                                     { W = (const float*)d_in[2]; bias = (const float*)d_in[3]; }
    float* out = (float*)d_out;

    scan16_kernel<<<BATCH * NH, 256>>>(f0);
    const int total = BATCH * TU;
    nsf_kernel<<<(total + 255) / 256, 256>>>(f0, W, bias, out);
}

// round 8
// speedup vs baseline: 1.2843x; 1.0586x over previous
#include <cuda_runtime.h>
#include <cstdint>

#define TU      204800     // 400 * 512 upsampled length
#define TBLK    400        // frames
#define BATCH   16
#define NH      9          // harmonic_num + 1
#define NROW1   12800      // TU / 16

// Level-1 inclusive prefix (cumsum of 16-sample row totals), per (b,h): 12800 each.
__device__ float g_P[BATCH * NH * NROW1];            // 7.4 MB
// Sequential multiples s_{k+1}(x) (acc=0 left-to-right), per (b,h,t): 16 each.
__device__ float g_seqx[BATCH * NH * TBLK * 16];     // 3.7 MB
// Runtime-opaque 1: forces mad.lo -> IMAD (fma pipe) for threefry adds.
__device__ uint32_t g_one = 1;

// a*b + c via IMAD (fma pipe), not IADD3 (alu pipe)
__device__ __forceinline__ uint32_t madd(uint32_t a, uint32_t b, uint32_t c) {
    uint32_t d;
    asm("mad.lo.s32 %0, %1, %2, %3;" : "=r"(d) : "r"(a), "r"(b), "r"(c));
    return d;
}

// ---------------- threefry2x32, key = (0, 42), counter (0, n) ----------------
// bits = x0_final ^ x1_final  (partitionable path, bit_width=32)
__device__ __forceinline__ uint32_t noise_bits(uint32_t n, uint32_t one,
                                               uint32_t kK, uint32_t kK1,
                                               uint32_t kK4, uint32_t k42,
                                               uint32_t k2, uint32_t k45, uint32_t k5) {
    uint32_t x0 = 0u, x1 = n + 42u;
#define TFR(r) { x0 = madd(x1, one, x0); x1 = __funnelshift_l(x1, x1, (r)); x1 ^= x0; }
    TFR(13) TFR(15) TFR(26) TFR(6)
    x0 = madd(one, k42, x0);  x1 = madd(one, kK1, x1);   // +ks1, +ks2+1
    TFR(17) TFR(29) TFR(16) TFR(24)
    x0 = madd(one, kK, x0);   x1 = madd(one, k2, x1);    // +ks2, +ks0+2
    TFR(13) TFR(15) TFR(26) TFR(6)
    /* x0 += ks0 = 0 */       x1 = madd(one, k45, x1);   // +ks1+3
    TFR(17) TFR(29) TFR(16) TFR(24)
    x0 = madd(one, k42, x0);  x1 = madd(one, kK4, x1);   // +ks1, +ks2+4
    TFR(13) TFR(15) TFR(26) TFR(6)
    x0 = madd(one, kK, x0);   x1 = madd(one, k5, x1);    // +ks2, +ks0+5
#undef TFR
    return x0 ^ x1;
}

// ---------------- MUFU helpers ----------------
__device__ __forceinline__ float mufu_sin(float r) {
    float v; asm("sin.approx.f32 %0, %1;" : "=f"(v) : "f"(r)); return v;
}
__device__ __forceinline__ float mufu_lg2(float t) {
    float v; asm("lg2.approx.f32 %0, %1;" : "=f"(v) : "f"(t)); return v;
}
__device__ __forceinline__ float mufu_ex2(float t) {
    float v; asm("ex2.approx.f32 %0, %1;" : "=f"(v) : "f"(t)); return v;
}
__device__ __forceinline__ float mufu_rcp(float t) {
    float v; asm("rcp.approx.f32 %0, %1;" : "=f"(v) : "f"(t)); return v;
}

// ---------------- Giles erfinv-based normal, WITHOUT the sqrt(2) factor ----------------
// Returns p*u; caller folds sqrt(2) (and noise_amp) into the merge-weight scale.
__device__ __forceinline__ float normal_pu(uint32_t bits) {
    float u2 = __uint_as_float((bits >> 9) | 0x40000000u);   // = 2*u01 + 2, exact
    const float lo = -0.99999994039535522461f;                // nextafter(-1,0)
    float u = __fadd_rn(__fadd_rn(u2, -2.0f), lo);            // fl(2*u01 + lo), u >= lo
    float t = fmaf(-u, u, 1.0f);                              // 1 - u^2  (> 0)
    float w = __fmul_rn(mufu_lg2(t), -0.6931471805599453f);   // -ln(1-u^2)
    float p;
    if (w < 5.0f) {
        w = w - 2.5f;
        p = 2.81022636e-08f;
        p = fmaf(p, w, 3.43273939e-07f);
        p = fmaf(p, w, -3.5233877e-06f);
        p = fmaf(p, w, -4.39150654e-06f);
        p = fmaf(p, w, 0.00021858087f);
        p = fmaf(p, w, -0.00125372503f);
        p = fmaf(p, w, -0.00417768164f);
        p = fmaf(p, w, 0.246640727f);
        p = fmaf(p, w, 1.50140941f);
    } else {
        w = sqrtf(w) - 3.0f;
        p = -0.000200214257f;
        p = fmaf(p, w, 0.000100950558f);
        p = fmaf(p, w, 0.00134934322f);
        p = fmaf(p, w, -0.00367342844f);
        p = fmaf(p, w, 0.00573950773f);
        p = fmaf(p, w, -0.0076224613f);
        p = fmaf(p, w, 0.00943887047f);
        p = fmaf(p, w, 1.00167406f);
        p = fmaf(p, w, 2.83297682f);
    }
    return __fmul_rn(p, u);
}

// ---------------- sin(phase), phase = fl(2*pi*C) >= 0, phase < 1.2e5 ----------------
// Magic-number round-to-int (RN) + 2-term Cody-Waite (P2 full f32 precision).
// Arg error <= ~5e-7 rad; MUFU sin on |r'| <= 3pi/4.
__device__ __forceinline__ float sin_phase(float phase) {
    const float MAGIC = 12582912.0f;                 // 1.5 * 2^23
    float tmp = fmaf(phase, 0.6366197723675814f, MAGIC);
    uint32_t q = __float_as_uint(tmp);               // low mantissa bits = k
    float fk = tmp - MAGIC;                          // exact: RN-to-integer of phase*2/pi
    float r = fmaf(fk, -1.5703125f, phase);          // exact (P1 has 9 mantissa bits, fk<2^15)
    r = fmaf(fk, -4.8382679489662e-4f, r);           // P2 = pi/2 - P1, one rounding
    float rr = (q & 1u) ? (1.5707963267948966f - r) : r;
    float v = mufu_sin(rr);
    return (q & 2u) ? -v : v;
}

// ---------------- fast tanh: ex2 + rcp (abs err ~1.2e-7) ----------------
__device__ __forceinline__ float tanh_fast(float z) {
    float a = fminf(fabsf(z) * 2.8853900817779268f, 64.0f);  // 2|z|*log2(e), clamped
    float e = mufu_ex2(a);                                    // exp(2|z|)
    float th = __fmul_rn(e - 1.0f, mufu_rcp(e + 1.0f));
    return copysignf(th, z);
}

// ---------------- Kernel 1: XLA ReduceWindowRewriter radix-16 scan (unchanged) ----------------
__global__ void scan16_kernel(const float* __restrict__ f0) {
    __shared__ float sm16[TBLK];
    __shared__ float U[TBLK];
    __shared__ float smT1[TBLK * 16];
    __shared__ float inner3[800];
    __shared__ float O2s[800];
    __shared__ float T3[50];
    __shared__ float O3s[50];
    __shared__ float inner4[50];

    const int row = blockIdx.x;                 // 0..143 = b*9+h
    const int b = row / NH, h = row % NH;
    const float m = (float)(h + 1);

    for (int t = threadIdx.x; t < TBLK; t += blockDim.x) {
        float x = __fmul_rn(__fdiv_rn(f0[b * TBLK + t], 48000.0f), m);
        float s = 0.0f;
#pragma unroll
        for (int k = 0; k < 16; k++) {
            s = __fadd_rn(s, x);
            g_seqx[(row * TBLK + t) * 16 + k] = s;
        }
        sm16[t] = s;
    }
    __syncthreads();

    for (int t = threadIdx.x; t < TBLK; t += blockDim.x) {
        float v = sm16[t], s = 0.0f;
#pragma unroll
        for (int k = 0; k < 16; k++) {
            s = __fadd_rn(s, v);
            smT1[t * 16 + k] = s;
        }
        U[t] = s;
    }
    __syncthreads();

    for (int R3 = threadIdx.x; R3 < 50; R3 += blockDim.x) {
        float s = 0.0f;
        for (int j = 0; j < 16; j++) {
            s = __fadd_rn(s, U[(16 * R3 + j) >> 1]);
            inner3[R3 * 16 + j] = s;
        }
        T3[R3] = s;
    }
    __syncthreads();

    if (threadIdx.x == 0) {
        float T4[4], O4[4];
        for (int r = 0; r < 4; r++) {
            float s = 0.0f;
            for (int j = 0; j < 16; j++) {
                int idx = 16 * r + j;
                float v = (idx < 50) ? T3[idx] : 0.0f;
                s = __fadd_rn(s, v);
                if (idx < 50) inner4[idx] = s;
            }
            T4[r] = s;
        }
        float s = 0.0f;
        for (int r = 0; r < 4; r++) { s = __fadd_rn(s, T4[r]); O4[r] = s; }
        for (int i = 0; i < 50; i++) {
            float e = ((i >> 4) == 0) ? 0.0f : O4[(i >> 4) - 1];
            O3s[i] = __fadd_rn(inner4[i], e);
        }
    }
    __syncthreads();

    for (int i2 = threadIdx.x; i2 < 800; i2 += blockDim.x) {
        float e = ((i2 >> 4) == 0) ? 0.0f : O3s[(i2 >> 4) - 1];
        O2s[i2] = __fadd_rn(inner3[i2], e);
    }
    __syncthreads();

    for (int R = threadIdx.x; R < NROW1; R += blockDim.x) {
        int t = R >> 5, k = R & 15, R2 = R >> 4;
        float e = (R2 == 0) ? 0.0f : O2s[R2 - 1];
        g_P[row * NROW1 + R] = __fadd_rn(smT1[t * 16 + k], e);
    }
}

// ---------------- Kernel 2: per-sample pipeline ----------------
__global__ void __launch_bounds__(256) nsf_kernel(const float* __restrict__ f0,
                                                  const float* __restrict__ W,
                                                  const float* __restrict__ bias,
                                                  float* __restrict__ out) {
    const int g = blockIdx.x * blockDim.x + threadIdx.x;
    if (g >= BATCH * TU) return;
    const int b = g / TU;
    const int s = g - b * TU;
    const int t = s >> 9;
    const int R = s >> 4;
    const int j = s & 15;

    const uint32_t one = g_one;
    const uint32_t kK  = 0x1BD11BDAu ^ 42u;
    const uint32_t kK1 = kK + 1u, kK4 = kK + 4u;
    const uint32_t k42 = 42u, k2 = 2u, k45 = 45u, k5 = 5u;

    const float f0t  = __ldg(&f0[b * TBLK + t]);
    const bool voiced = (f0t > 1.0f);

    const uint32_t nbase = (uint32_t)g * (uint32_t)NH;

    float accS = 0.0f, accN = 0.0f;
#pragma unroll
    for (int h = 0; h < NH; h++) {
        const int row = b * NH + h;
        const float inner0 = __ldg(&g_seqx[(row * TBLK + t) * 16 + j]);
        const float pre = (R == 0) ? 0.0f : __ldg(&g_P[row * NROW1 + R - 1]);
        const float C = __fadd_rn(inner0, pre);

        const float phase = __fmul_rn(C, 6.283185307179586f);   // matches reference rounding
        const float sv = sin_phase(phase);

        const uint32_t bits = noise_bits(nbase + (uint32_t)h, one, kK, kK1, kK4, k42, k2, k45, k5);
        const float pu = normal_pu(bits);

        const float wh = __ldg(&W[h]);
        accS = fmaf(sv, wh, accS);
        accN = fmaf(pu, wh, accN);
    }

    // noise scale: noise_amp * sqrt(2); sine scale: SINE_AMP * uv
    const float namp2 = voiced ? 0.0042426406871192851f   // 0.003  * sqrt(2)
                               : 0.047140452079103173f;   // 0.1/3  * sqrt(2)
    float z = fmaf(accN, namp2, __ldg(&bias[0]));
    if (voiced) z = fmaf(accS, 0.1f, z);
    out[g] = tanh_fast(z);
}

extern "C" void kernel_launch(void* const* d_in, const int* in_sizes, int n_in,
                              void* d_out, int out_size) {
    const float* f0 = (const float*)d_in[0];
    const float* W;
    const float* bias;
    if (n_in >= 4 && in_sizes[2] == NH)      { W = (const float*)d_in[2]; bias = (const float*)d_in[3]; }
    else if (n_in >= 3 && in_sizes[1] == NH) { W = (const float*)d_in[1]; bias = (const float*)d_in[2]; }
    else                                     { W = (const float*)d_in[2]; bias = (const float*)d_in[3]; }
    float* out = (float*)d_out;

    scan16_kernel<<<BATCH * NH, 256>>>(f0);
    const int total = BATCH * TU;
    nsf_kernel<<<(total + 255) / 256, 256>>>(f0, W, bias, out);
}